// round 15
// baseline (speedup 1.0000x reference)
#include <cuda_runtime.h>
#include <cuda_bf16.h>
#include <cstdint>
#include <cstddef>

// ---------------- dims ----------------
#define BB   2
#define NN   256
#define DN   128
#define DE   64
#define DH   128
#define HH   8
#define DHH  16
#define DNH  512
#define DEH  256
#define LL   2

#define SCALE 0.08838834764831845f   // 1/sqrt(128)

typedef unsigned long long ull;

// ---------------- packed f32x2 helpers ----------------
__device__ __forceinline__ ull fma2(ull a, ull b, ull c) {
    ull d;
    asm("fma.rn.f32x2 %0, %1, %2, %3;" : "=l"(d) : "l"(a), "l"(b), "l"(c));
    return d;
}
__device__ __forceinline__ ull dup2f(float x) {
    ull r; asm("mov.b64 %0, {%1, %1};" : "=l"(r) : "f"(x)); return r;
}
__device__ __forceinline__ float2 unpk(ull v) {
    float2 r; asm("mov.b64 {%0, %1}, %2;" : "=f"(r.x), "=f"(r.y) : "l"(v)); return r;
}

__device__ __forceinline__ float gelu_f(float x) {
    return 0.5f * x * (1.0f + erff(x * 0.70710678118654752440f));
}

// ---------------- persistent scratch ----------------
__device__ float g_x[BB*NN*DN];
__device__ float g_qkvn[BB*NN*3*DH];
__device__ float g_ao[BB*NN*DH];
__device__ float g_s[BB*NN*DEH];
__device__ float g_t[BB*NN*DEH];
__device__ float g_ebuf1[(size_t)BB*NN*NN*DE];
__device__ float g_ebuf0[(size_t)BB*NN*NN*DE];

// ---------------- k_copy_x ----------------
__global__ void k_copy_x(const float* __restrict__ node) {
    int i = blockIdx.x * blockDim.x + threadIdx.x;
    if (i < BB*NN*DN) g_x[i] = node[i];
}

// ---------------- k_qkvn : FFMA2, 256 threads (192 active) ----------------
__global__ void __launch_bounds__(256)
k_qkvn(const float* __restrict__ W) {
    __shared__ float xs[DN];
    int row = blockIdx.x, tid = threadIdx.x;
    if (tid < 128) xs[tid] = g_x[row*DN + tid];
    __syncthreads();
    if (tid < 192) {
        const ull* W2 = (const ull*)W;   // [128][192] ull cols
        ull acc = 0ull;
#pragma unroll 8
        for (int k = 0; k < 128; k++)
            acc = fma2(dup2f(xs[k]), W2[k*192 + tid], acc);
        float2 f = unpk(acc);
        ((float2*)(g_qkvn + row*384))[tid] = f;
    }
}

// ================= k_attn1 : fused edge-qkv GEMM + dots + v + softmax + AV =================
// grid 512 (b*N+i), 512 threads.
// smem (floats):
//  Ws    [0,32768)            Wqkv_e 64x512
//  ed    [32768,33792)        ull[64][8]
//  qkvs  [33792,37888)        ull[8][256]
//  dots  [37888,39936)        [8][256]
//  vsm   [39936,56320)        bf16[256][128]
//  qns   [56320,56448)
//  invs  [56448,56456)
//  pav   [56456,56968)        [4][128]
#define A1_SMEM_F 56968
__global__ void __launch_bounds__(512, 1)
k_attn1(const float* __restrict__ e_in, const float* __restrict__ W) {
    extern __shared__ float sm[];
    float* Ws   = sm;
    ull*   Ws2  = (ull*)Ws;
    ull*   ed   = (ull*)(sm + 32768);
    float* qkvs = sm + 33792;
    ull*   qkvs2 = (ull*)qkvs;
    float* dots = sm + 37888;
    __nv_bfloat16* vsm = (__nv_bfloat16*)(sm + 39936);
    float* qns  = sm + 56320;
    float* invs = sm + 56448;
    float* pav  = sm + 56456;

    int bi = blockIdx.x, b = bi >> 8, tid = threadIdx.x;

    {   // weights: 8192 float4 / 512 threads = 16 each
        const float4* Wg = (const float4*)W;
        float4* Wd = (float4*)Ws;
#pragma unroll
        for (int it = 0; it < 16; it++) Wd[tid + it*512] = Wg[tid + it*512];
    }
    if (tid < 128) qns[tid] = g_qkvn[bi*384 + (tid>>4)*48 + (tid&15)];

    int sj = tid >> 6, skk = tid & 63;   // staging: 1 value/thread
    float r0 = e_in[((size_t)bi*NN + sj)*DE + skk];
    __syncthreads();

    int c = tid & 255, g = tid >> 8;     // GEMM map: col pair, j-group of 4
    int hd = tid & 127, jrg = tid >> 7;  // epilogue map: (h,d), j-group of 2
    int h = hd >> 4, d = hd & 15;

    for (int j0 = 0; j0 < NN; j0 += 8) {
        ed[skk*8 + sj] = dup2f(r0);
        __syncthreads();
        if (j0 + 8 < NN)
            r0 = e_in[((size_t)bi*NN + (j0+8+sj))*DE + skk];

        // GEMM: 4 accumulators (j = g*4 + 0..3)
        ull a0=0,a1=0,a2=0,a3=0;
#pragma unroll
        for (int k = 0; k < 64; k++) {
            ull w = Ws2[k*256 + c];
            ulonglong2 ea = *(const ulonglong2*)(ed + k*8 + g*4);
            ulonglong2 eb = *(const ulonglong2*)(ed + k*8 + g*4 + 2);
            a0 = fma2(ea.x, w, a0); a1 = fma2(ea.y, w, a1);
            a2 = fma2(eb.x, w, a2); a3 = fma2(eb.y, w, a3);
        }
        qkvs2[(g*4+0)*256 + c] = a0;
        qkvs2[(g*4+1)*256 + c] = a1;
        qkvs2[(g*4+2)*256 + c] = a2;
        qkvs2[(g*4+3)*256 + c] = a3;
        __syncthreads();

        // epilogue: (h,d) x 2 j per thread
        float qn = qns[hd];
#pragma unroll
        for (int s = 0; s < 2; s++) {
            int jr = jrg*2 + s, j = j0 + jr;
            const float* qv = qkvs + jr*512 + h*64 + d;
            float eq = qv[0], ek = qv[16], ev = qv[32], em = qv[48];
            const float* kv = g_qkvn + (size_t)(b*NN + j)*384 + h*48 + d;
            float kn = kv[16], vn = kv[32];
            float pd = (qn + eq) * (kn + ek);
            pd += __shfl_xor_sync(0xffffffffu, pd, 8);
            pd += __shfl_xor_sync(0xffffffffu, pd, 4);
            pd += __shfl_xor_sync(0xffffffffu, pd, 2);
            pd += __shfl_xor_sync(0xffffffffu, pd, 1);
            if (d == 0) dots[h*256 + j] = pd * SCALE;
            vsm[j*128 + hd] = __float2bfloat16(vn*em + ev);
        }
        __syncthreads();
    }

    // softmax: warp w = head w (first 8 warps)
    {
        int wid = tid >> 5, lane = tid & 31;
        if (wid < 8) {
            float* dr = dots + wid*256;
            float vr[8]; float m = -1e30f;
#pragma unroll
            for (int q = 0; q < 8; q++) { vr[q] = dr[q*32 + lane]; m = fmaxf(m, vr[q]); }
#pragma unroll
            for (int o = 16; o; o >>= 1) m = fmaxf(m, __shfl_xor_sync(0xffffffffu, m, o));
            float s = 0.f;
#pragma unroll
            for (int q = 0; q < 8; q++) { float p = __expf(vr[q] - m); dr[q*32 + lane] = p; s += p; }
#pragma unroll
            for (int o = 16; o; o >>= 1) s += __shfl_xor_sync(0xffffffffu, s, o);
            if (lane == 0) invs[wid] = 1.f/s;
        }
    }
    __syncthreads();

    // AV: thread (hd, quarter), 64 j each
    {
        int qtr = tid >> 7;
        const float* pr = dots + h*256 + qtr*64;
        const __nv_bfloat16* vp = vsm + (size_t)qtr*64*128 + hd;
        float acc = 0.f;
#pragma unroll 8
        for (int jj = 0; jj < 64; jj++)
            acc += pr[jj] * __bfloat162float(vp[jj*128]);
        pav[qtr*128 + hd] = acc;
    }
    __syncthreads();
    if (tid < 128)
        g_ao[bi*128 + tid] = (pav[tid] + pav[128+tid] + pav[256+tid] + pav[384+tid]) * invs[tid>>4];
}

// ---------------- k_attn2 : Wo + Wl0 + LN + node MLP + LN (FFMA2, 256 thr) ----------------
__global__ void __launch_bounds__(256)
k_attn2(const float* __restrict__ Wo, const float* __restrict__ bo,
        const float* __restrict__ Wl0, const float* __restrict__ bl0,
        const float* __restrict__ g0, const float* __restrict__ b0,
        const float* __restrict__ Wm1, const float* __restrict__ Wm2,
        const float* __restrict__ bm2,
        const float* __restrict__ g1, const float* __restrict__ b1) {
    __shared__ float outs[DH];
    __shared__ float asv[DH];
    __shared__ float xs[DN];
    __shared__ float hid[DNH];
    __shared__ ull psum[256];    // [4][64]
    __shared__ float red[8];

    int bi = blockIdx.x, tid = threadIdx.x;
    int c2 = tid & 63, ks = tid >> 6;
    int pr2 = tid >> 1, sel = tid & 1;
    int w = tid >> 5;

    if (tid < 128) outs[tid] = g_ao[bi*128 + tid];
    __syncthreads();

    // ao = outs @ Wo (+bo)
    {
        const ull* W2 = (const ull*)Wo;
        ull acc = 0ull;
#pragma unroll 8
        for (int kk = 0; kk < 32; kk++) {
            int k = ks*32 + kk;
            acc = fma2(dup2f(outs[k]), W2[k*64 + c2], acc);
        }
        psum[ks*64 + c2] = acc;
    }
    __syncthreads();
    if (tid < 128) {
        float v = 0.f;
#pragma unroll
        for (int t = 0; t < 4; t++) { float2 f = unpk(psum[t*64 + pr2]); v += sel ? f.y : f.x; }
        asv[tid] = v + bo[tid];
    }
    __syncthreads();

    // y = asv @ Wl0 (+bl0), xv = x + y
    {
        const ull* W2 = (const ull*)Wl0;
        ull acc = 0ull;
#pragma unroll 8
        for (int kk = 0; kk < 32; kk++) {
            int k = ks*32 + kk;
            acc = fma2(dup2f(asv[k]), W2[k*64 + c2], acc);
        }
        psum[ks*64 + c2] = acc;
    }
    __syncthreads();
    float xv = 0.f;
    if (tid < 128) {
        float v = 0.f;
#pragma unroll
        for (int t = 0; t < 4; t++) { float2 f = unpk(psum[t*64 + pr2]); v += sel ? f.y : f.x; }
        xv = g_x[bi*128 + tid] + v + bl0[tid];
        float s1 = xv, s2 = xv*xv;
#pragma unroll
        for (int o = 16; o; o >>= 1) { s1 += __shfl_xor_sync(0xffffffffu, s1, o); s2 += __shfl_xor_sync(0xffffffffu, s2, o); }
        if ((tid & 31) == 0) { red[w*2] = s1; red[w*2+1] = s2; }
    }
    __syncthreads();
    if (tid < 128) {
        float s1 = red[0]+red[2]+red[4]+red[6];
        float s2 = red[1]+red[3]+red[5]+red[7];
        float mean = s1 * (1.0f/DN);
        float var  = s2 * (1.0f/DN) - mean*mean;
        xs[tid] = (xv - mean) * rsqrtf(var + 1e-5f) * g0[tid] + b0[tid];
    }
    __syncthreads();

    // hid = gelu(x1 @ Wm1): thread = ull col (256)
    {
        const ull* W2 = (const ull*)Wm1;
        ull acc = 0ull;
#pragma unroll 8
        for (int k = 0; k < 128; k++)
            acc = fma2(dup2f(xs[k]), W2[k*256 + tid], acc);
        float2 f = unpk(acc);
        hid[2*tid]   = gelu_f(f.x);
        hid[2*tid+1] = gelu_f(f.y);
    }
    __syncthreads();

    // o2 = hid @ Wm2 (+bm2): k=512, 4-way split
    {
        const ull* W2 = (const ull*)Wm2;
        ull acc = 0ull;
#pragma unroll 8
        for (int kk = 0; kk < 128; kk++) {
            int k = ks*128 + kk;
            acc = fma2(dup2f(hid[k]), W2[k*64 + c2], acc);
        }
        psum[ks*64 + c2] = acc;
    }
    __syncthreads();
    float x2 = 0.f;
    if (tid < 128) {
        float v = 0.f;
#pragma unroll
        for (int t = 0; t < 4; t++) { float2 f = unpk(psum[t*64 + pr2]); v += sel ? f.y : f.x; }
        x2 = xs[tid] + v + bm2[tid];
        float s1 = x2, s2 = x2*x2;
#pragma unroll
        for (int o = 16; o; o >>= 1) { s1 += __shfl_xor_sync(0xffffffffu, s1, o); s2 += __shfl_xor_sync(0xffffffffu, s2, o); }
        if ((tid & 31) == 0) { red[w*2] = s1; red[w*2+1] = s2; }
    }
    __syncthreads();
    if (tid < 128) {
        float s1 = red[0]+red[2]+red[4]+red[6];
        float s2 = red[1]+red[3]+red[5]+red[7];
        float mean = s1 * (1.0f/DN);
        float var  = s2 * (1.0f/DN) - mean*mean;
        g_x[bi*128 + tid] = (x2 - mean) * rsqrtf(var + 1e-5f) * g1[tid] + b1[tid];
    }
}

// ---------------- k_srctgt : FFMA2 ----------------
__global__ void __launch_bounds__(256)
k_srctgt(const float* __restrict__ Wsm, const float* __restrict__ bsv,
         const float* __restrict__ Wtm, const float* __restrict__ btv) {
    __shared__ float xs[DN];
    int row = blockIdx.x, tid = threadIdx.x;
    if (tid < 128) xs[tid] = g_x[row*DN + tid];
    __syncthreads();
    int cc = tid & 127;
    bool isT = tid >= 128;
    const ull* W2 = (const ull*)(isT ? Wtm : Wsm);
    ull acc = 0ull;
#pragma unroll 8
    for (int k = 0; k < 128; k++)
        acc = fma2(dup2f(xs[k]), W2[k*128 + cc], acc);
    float2 f = unpk(acc);
    const float2* bv = (const float2*)(isT ? btv : bsv);
    float2 b2 = bv[cc];
    float* dst = isT ? g_t : g_s;
    float2 o2 = { f.x + b2.x, f.y + b2.y };
    ((float2*)(dst + row*DEH))[cc] = o2;
}

// ================= k_e1 : fused edge MLP1 + residual + LN (512 threads) =================
// smem (floats):
//  W0s   [0,32768)        We0 128x256
//  W1s   [32768,49152)    We1 256x64
//  ecatd [49152,51200)    ull[128][8]
//  hiddp [51200,55552)    ull[128][17]
//  psum  [55552,57600)    ull[4][8][32]
//  srcs  [57600,57856)
#define E1_SMEM_F 57856
__global__ void __launch_bounds__(512, 1)
k_e1(const float* __restrict__ e_in, float* __restrict__ e_out,
     const float* __restrict__ We0, const float* __restrict__ be0,
     const float* __restrict__ We1, const float* __restrict__ be1,
     const float* __restrict__ g0, const float* __restrict__ b0) {
    extern __shared__ float sm[];
    float* W0s = sm;          ull* W0s2 = (ull*)W0s;
    float* W1s = sm + 32768;  ull* W1s2 = (ull*)W1s;
    ull* ecatd = (ull*)(sm + 49152);
    ull* hiddp = (ull*)(sm + 51200);
    ull* psum  = (ull*)(sm + 55552);
    float* srcs = sm + 57600;

    int bi = blockIdx.x, b = bi >> 8, i = bi & 255, tid = threadIdx.x;

    {
        const float4* w0 = (const float4*)We0; float4* d0 = (float4*)W0s;
#pragma unroll
        for (int it = 0; it < 16; it++) d0[tid + it*512] = w0[tid + it*512];
        const float4* w1 = (const float4*)We1; float4* d1 = (float4*)W1s;
#pragma unroll
        for (int it = 0; it < 8; it++) d1[tid + it*512] = w1[tid + it*512];
    }
    if (tid < 256) srcs[tid] = g_s[bi*DEH + tid] + be0[tid];

    // staging: 1024 vals = 2/thread
    float rv[2];
#pragma unroll
    for (int it = 0; it < 2; it++) {
        int idx = tid + it*512, j = idx >> 7, kk = idx & 127;
        rv[it] = (kk < 64) ? e_in[((size_t)bi*NN + j)*DE + kk]
                           : e_in[(((size_t)b*NN + j)*NN + i)*DE + (kk - 64)];
    }
    __syncthreads();

    int cp1 = tid & 127, jg = tid >> 7;                    // phase1: 2 j each
    int c2p = tid & 31, jg2 = (tid >> 5) & 3, ks = tid >> 7; // phase2: 2 j each, 4 k-splits
    int jc = tid >> 5, cpc = tid & 31;                     // combine (jc<8)

    for (int j0 = 0; j0 < NN; j0 += 8) {
#pragma unroll
        for (int it = 0; it < 2; it++) {
            int idx = tid + it*512, j = idx >> 7, kk = idx & 127;
            ecatd[kk*8 + j] = dup2f(rv[it]);
        }
        __syncthreads();
        if (j0 + 8 < NN) {
#pragma unroll
            for (int it = 0; it < 2; it++) {
                int idx = tid + it*512, j = (idx >> 7) + j0 + 8, kk = idx & 127;
                rv[it] = (kk < 64) ? e_in[((size_t)bi*NN + j)*DE + kk]
                                   : e_in[(((size_t)b*NN + j)*NN + i)*DE + (kk - 64)];
            }
        }
        // phase1: hid col pair cp1, 2 j
        ull acc0, acc1;
        {
            float2 sv = ((const float2*)srcs)[cp1];
            float2 tv0 = ((const float2*)(g_t + (size_t)(b*NN + j0 + jg*2 + 0)*DEH))[cp1];
            float2 tv1 = ((const float2*)(g_t + (size_t)(b*NN + j0 + jg*2 + 1)*DEH))[cp1];
            float2 i0 = { sv.x + tv0.x, sv.y + tv0.y };
            float2 i1 = { sv.x + tv1.x, sv.y + tv1.y };
            acc0 = *(const ull*)&i0;
            acc1 = *(const ull*)&i1;
        }
#pragma unroll
        for (int k = 0; k < 128; k++) {
            ull w = W0s2[k*128 + cp1];
            ulonglong2 ea = *(const ulonglong2*)(ecatd + k*8 + jg*2);
            acc0 = fma2(ea.x, w, acc0);
            acc1 = fma2(ea.y, w, acc1);
        }
        {
            float2 f0 = unpk(acc0), f1 = unpk(acc1);
            int j0l = jg*2, j1l = jg*2 + 1;
            hiddp[cp1*17 + j0l*2 + 0] = dup2f(gelu_f(f0.x));
            hiddp[cp1*17 + j0l*2 + 1] = dup2f(gelu_f(f0.y));
            hiddp[cp1*17 + j1l*2 + 0] = dup2f(gelu_f(f1.x));
            hiddp[cp1*17 + j1l*2 + 1] = dup2f(gelu_f(f1.y));
        }
        __syncthreads();

        // phase2: out col pair c2p, 2 j, 4-way k-split
        {
            ull p0 = 0ull, p1 = 0ull;
            int kb = ks*64;
#pragma unroll
            for (int kk = 0; kk < 64; kk++) {
                int k = kb + kk;
                ull w = W1s2[k*32 + c2p];
                const ull* hp = hiddp + (k>>1)*17 + (k&1) + jg2*4;
                p0 = fma2(hp[0], w, p0);
                p1 = fma2(hp[2], w, p1);
            }
            psum[(ks*8 + jg2*2 + 0)*32 + c2p] = p0;
            psum[(ks*8 + jg2*2 + 1)*32 + c2p] = p1;
        }
        __syncthreads();

        // combine + residual + LN: warps 0..7, warp = one j
        if (jc < 8) {
            float2 q0 = unpk(psum[(0*8 + jc)*32 + cpc]);
            float2 q1 = unpk(psum[(1*8 + jc)*32 + cpc]);
            float2 q2 = unpk(psum[(2*8 + jc)*32 + cpc]);
            float2 q3 = unpk(psum[(3*8 + jc)*32 + cpc]);
            float2 bia = ((const float2*)be1)[cpc];
            float2 res = ((const float2*)(e_in + ((size_t)bi*NN + j0 + jc)*DE))[cpc];
            float r0 = q0.x + q1.x + q2.x + q3.x + bia.x + res.x;
            float r1 = q0.y + q1.y + q2.y + q3.y + bia.y + res.y;
            float s1 = r0 + r1, s2 = r0*r0 + r1*r1;
#pragma unroll
            for (int o = 16; o; o >>= 1) {
                s1 += __shfl_xor_sync(0xffffffffu, s1, o);
                s2 += __shfl_xor_sync(0xffffffffu, s2, o);
            }
            float mean = s1 * (1.f/DE);
            float var  = s2 * (1.f/DE) - mean*mean;
            float rs = rsqrtf(var + 1e-5f);
            float2 gg = ((const float2*)g0)[cpc];
            float2 bb = ((const float2*)b0)[cpc];
            float2 o2 = { (r0 - mean)*rs*gg.x + bb.x, (r1 - mean)*rs*gg.y + bb.y };
            ((float2*)(e_out + ((size_t)bi*NN + j0 + jc)*DE))[cpc] = o2;
        }
        __syncthreads();
    }
}

// ================= k_e2 : fused edge MLP2 + residual + LN, in place (512 threads) =================
// smem (floats):
//  W1s   [0,16384)       Wem1 64x256
//  W2s   [16384,32768)   Wem2 256x64
//  ed    [32768,33792)   ull[64][8]
//  hiddp [33792,38144)   ull[128][17]
//  psum  [38144,40192)   ull[4][8][32]
#define E2_SMEM_F 40192
__global__ void __launch_bounds__(512, 1)
k_e2(float* __restrict__ e_io,
     const float* __restrict__ Wem1, const float* __restrict__ Wem2,
     const float* __restrict__ bem2,
     const float* __restrict__ g1, const float* __restrict__ b1) {
    extern __shared__ float sm[];
    float* W1s = sm;          ull* W1s2 = (ull*)W1s;
    float* W2s = sm + 16384;  ull* W2s2 = (ull*)W2s;
    ull* ed    = (ull*)(sm + 32768);
    ull* hiddp = (ull*)(sm + 33792);
    ull* psum  = (ull*)(sm + 38144);

    int bi = blockIdx.x, tid = threadIdx.x;
    {
        const float4* w1 = (const float4*)Wem1; float4* d1 = (float4*)W1s;
#pragma unroll
        for (int it = 0; it < 8; it++) d1[tid + it*512] = w1[tid + it*512];
        const float4* w2 = (const float4*)Wem2; float4* d2 = (float4*)W2s;
#pragma unroll
        for (int it = 0; it < 8; it++) d2[tid + it*512] = w2[tid + it*512];
    }
    int sj = tid >> 6, skk = tid & 63;
    sj &= 7;
    float r0 = e_io[((size_t)bi*NN + sj)*DE + skk];
    __syncthreads();

    int cp1 = tid & 127, jg = tid >> 7;
    int c2p = tid & 31, jg2 = (tid >> 5) & 3, ks = tid >> 7;
    int jc = tid >> 5, cpc = tid & 31;

    for (int j0 = 0; j0 < NN; j0 += 8) {
        ed[skk*8 + sj] = dup2f(r0);
        __syncthreads();
        if (j0 + 8 < NN)
            r0 = e_io[((size_t)bi*NN + (j0+8+sj))*DE + skk];

        // phase1: k=64, 2 j
        {
            ull acc0 = 0ull, acc1 = 0ull;
#pragma unroll
            for (int k = 0; k < 64; k++) {
                ull w = W1s2[k*128 + cp1];
                ulonglong2 ea = *(const ulonglong2*)(ed + k*8 + jg*2);
                acc0 = fma2(ea.x, w, acc0);
                acc1 = fma2(ea.y, w, acc1);
            }
            float2 f0 = unpk(acc0), f1 = unpk(acc1);
            int j0l = jg*2, j1l = jg*2 + 1;
            hiddp[cp1*17 + j0l*2 + 0] = dup2f(gelu_f(f0.x));
            hiddp[cp1*17 + j0l*2 + 1] = dup2f(gelu_f(f0.y));
            hiddp[cp1*17 + j1l*2 + 0] = dup2f(gelu_f(f1.x));
            hiddp[cp1*17 + j1l*2 + 1] = dup2f(gelu_f(f1.y));
        }
        __syncthreads();

        // phase2: k=256, 4-way split, 2 j
        {
            ull p0 = 0ull, p1 = 0ull;
            int kb = ks*64;
#pragma unroll
            for (int kk = 0; kk < 64; kk++) {
                int k = kb + kk;
                ull w = W2s2[k*32 + c2p];
                const ull* hp = hiddp + (k>>1)*17 + (k&1) + jg2*4;
                p0 = fma2(hp[0], w, p0);
                p1 = fma2(hp[2], w, p1);
            }
            psum[(ks*8 + jg2*2 + 0)*32 + c2p] = p0;
            psum[(ks*8 + jg2*2 + 1)*32 + c2p] = p1;
        }
        __syncthreads();

        // combine + residual + LN
        if (jc < 8) {
            float2 q0 = unpk(psum[(0*8 + jc)*32 + cpc]);
            float2 q1 = unpk(psum[(1*8 + jc)*32 + cpc]);
            float2 q2 = unpk(psum[(2*8 + jc)*32 + cpc]);
            float2 q3 = unpk(psum[(3*8 + jc)*32 + cpc]);
            float2 bia = ((const float2*)bem2)[cpc];
            float2 res = ((const float2*)(e_io + ((size_t)bi*NN + j0 + jc)*DE))[cpc];
            float r0c = q0.x + q1.x + q2.x + q3.x + bia.x + res.x;
            float r1c = q0.y + q1.y + q2.y + q3.y + bia.y + res.y;
            float s1 = r0c + r1c, s2 = r0c*r0c + r1c*r1c;
#pragma unroll
            for (int o = 16; o; o >>= 1) {
                s1 += __shfl_xor_sync(0xffffffffu, s1, o);
                s2 += __shfl_xor_sync(0xffffffffu, s2, o);
            }
            float mean = s1 * (1.f/DE);
            float var  = s2 * (1.f/DE) - mean*mean;
            float rs = rsqrtf(var + 1e-5f);
            float2 gg = ((const float2*)g1)[cpc];
            float2 bb = ((const float2*)b1)[cpc];
            float2 o2 = { (r0c - mean)*rs*gg.x + bb.x, (r1c - mean)*rs*gg.y + bb.y };
            ((float2*)(e_io + ((size_t)bi*NN + j0 + jc)*DE))[cpc] = o2;
        }
        __syncthreads();
    }
}

// ---------------- k_final ----------------
__global__ void k_final(float* __restrict__ out) {
    int idx = blockIdx.x * blockDim.x + threadIdx.x;
    const int nx = BB*NN*DN;
    const int ne = BB*NN*NN*DE;
    if (idx < nx) out[idx] = g_x[idx];
    else if (idx < nx + ne) out[idx] = g_ebuf0[idx - nx];
}

// ---------------- launch ----------------
extern "C" void kernel_launch(void* const* d_in, const int* in_sizes, int n_in,
                              void* d_out, int out_size) {
    const float* node    = (const float*)d_in[0];
    const float* edge    = (const float*)d_in[1];
    const float* Wqkv_n  = (const float*)d_in[2];
    const float* Wqkv_e  = (const float*)d_in[3];
    const float* Wo      = (const float*)d_in[4];
    const float* bo      = (const float*)d_in[5];
    const float* Wl0     = (const float*)d_in[6];
    const float* bl0     = (const float*)d_in[7];
    const float* ln0_g   = (const float*)d_in[8];
    const float* ln0_b   = (const float*)d_in[9];
    const float* Wm1     = (const float*)d_in[10];
    const float* Wm2     = (const float*)d_in[11];
    const float* bm2     = (const float*)d_in[12];
    const float* ln1_g   = (const float*)d_in[13];
    const float* ln1_b   = (const float*)d_in[14];
    const float* We0     = (const float*)d_in[15];
    const float* be0     = (const float*)d_in[16];
    const float* Wsm     = (const float*)d_in[17];
    const float* bsv     = (const float*)d_in[18];
    const float* Wtm     = (const float*)d_in[19];
    const float* btv     = (const float*)d_in[20];
    const float* We1     = (const float*)d_in[21];
    const float* be1     = (const float*)d_in[22];
    const float* eln0_g  = (const float*)d_in[23];
    const float* eln0_b  = (const float*)d_in[24];
    const float* Wem1    = (const float*)d_in[25];
    const float* Wem2    = (const float*)d_in[26];
    const float* bem2    = (const float*)d_in[27];
    const float* eln1_g  = (const float*)d_in[28];
    const float* eln1_b  = (const float*)d_in[29];
    float* out = (float*)d_out;

    cudaFuncSetAttribute(k_attn1, cudaFuncAttributeMaxDynamicSharedMemorySize, A1_SMEM_F*4);
    cudaFuncSetAttribute(k_e1,    cudaFuncAttributeMaxDynamicSharedMemorySize, E1_SMEM_F*4);
    cudaFuncSetAttribute(k_e2,    cudaFuncAttributeMaxDynamicSharedMemorySize, E2_SMEM_F*4);

    float *pe0, *pe1;
    cudaGetSymbolAddress((void**)&pe0, g_ebuf0);
    cudaGetSymbolAddress((void**)&pe1, g_ebuf1);

    k_copy_x<<<(BB*NN*DN + 255)/256, 256>>>(node);

    const float* e_in = edge;
    float* e_out = pe1;

    for (int l = 0; l < LL; l++) {
        k_qkvn<<<BB*NN, 256>>>(Wqkv_n + (size_t)l*DN*3*DH);
        k_attn1<<<BB*NN, 512, A1_SMEM_F*4>>>(e_in, Wqkv_e + (size_t)l*DE*4*DH);
        k_attn2<<<BB*NN, 256>>>(Wo + (size_t)l*DH*DN, bo + (size_t)l*DN,
                                Wl0 + (size_t)l*DN*DN, bl0 + (size_t)l*DN,
                                ln0_g + (size_t)l*DN, ln0_b + (size_t)l*DN,
                                Wm1 + (size_t)l*DN*DNH, Wm2 + (size_t)l*DNH*DN,
                                bm2 + (size_t)l*DN,
                                ln1_g + (size_t)l*DN, ln1_b + (size_t)l*DN);
        k_srctgt<<<BB*NN, 256>>>(Wsm + (size_t)l*DN*DEH, bsv + (size_t)l*DEH,
                                 Wtm + (size_t)l*DN*DEH, btv + (size_t)l*DEH);
        k_e1<<<BB*NN, 512, E1_SMEM_F*4>>>(e_in, e_out,
                                          We0 + (size_t)l*2*DE*DEH, be0 + (size_t)l*DEH,
                                          We1 + (size_t)l*DEH*DE, be1 + (size_t)l*DE,
                                          eln0_g + (size_t)l*DE, eln0_b + (size_t)l*DE);
        k_e2<<<BB*NN, 512, E2_SMEM_F*4>>>(e_out,
                                          Wem1 + (size_t)l*DE*DEH, Wem2 + (size_t)l*DEH*DE,
                                          bem2 + (size_t)l*DE,
                                          eln1_g + (size_t)l*DE, eln1_b + (size_t)l*DE);
        e_in = e_out;
        e_out = pe0;
    }

    int total = BB*NN*DN + BB*NN*NN*DE;
    k_final<<<(total + 255)/256, 256>>>(out);
}

// round 16
// speedup vs baseline: 1.0412x; 1.0412x over previous
#include <cuda_runtime.h>
#include <cuda_bf16.h>
#include <cstdint>
#include <cstddef>

// ---------------- dims ----------------
#define BB   2
#define NN   256
#define DN   128
#define DE   64
#define DH   128
#define HH   8
#define DHH  16
#define DNH  512
#define DEH  256
#define LL   2

#define SCALE 0.08838834764831845f   // 1/sqrt(128)

typedef unsigned long long ull;

// ---------------- packed f32x2 helpers ----------------
__device__ __forceinline__ ull fma2(ull a, ull b, ull c) {
    ull d;
    asm("fma.rn.f32x2 %0, %1, %2, %3;" : "=l"(d) : "l"(a), "l"(b), "l"(c));
    return d;
}
__device__ __forceinline__ ull dup2f(float x) {
    ull r; asm("mov.b64 %0, {%1, %1};" : "=l"(r) : "f"(x)); return r;
}
__device__ __forceinline__ float2 unpk(ull v) {
    float2 r; asm("mov.b64 {%0, %1}, %2;" : "=f"(r.x), "=f"(r.y) : "l"(v)); return r;
}

__device__ __forceinline__ float gelu_f(float x) {
    return 0.5f * x * (1.0f + erff(x * 0.70710678118654752440f));
}

// ---------------- persistent scratch ----------------
__device__ float g_x[BB*NN*DN];
__device__ float g_qkvn[BB*NN*3*DH];
__device__ float g_ao[BB*NN*DH];
__device__ float g_s[BB*NN*DEH];
__device__ float g_t[BB*NN*DEH];
__device__ float g_ebuf1[(size_t)BB*NN*NN*DE];
__device__ float g_ebuf0[(size_t)BB*NN*NN*DE];

// ---------------- k_copy_x ----------------
__global__ void k_copy_x(const float* __restrict__ node) {
    int i = blockIdx.x * blockDim.x + threadIdx.x;
    if (i < BB*NN*DN) g_x[i] = node[i];
}

// ---------------- k_qkvn : FFMA2, 256 threads (192 active) ----------------
__global__ void __launch_bounds__(256)
k_qkvn(const float* __restrict__ W) {
    __shared__ float xs[DN];
    int row = blockIdx.x, tid = threadIdx.x;
    if (tid < 128) xs[tid] = g_x[row*DN + tid];
    __syncthreads();
    if (tid < 192) {
        const ull* W2 = (const ull*)W;   // [128][192] ull cols
        ull acc = 0ull;
#pragma unroll 8
        for (int k = 0; k < 128; k++)
            acc = fma2(dup2f(xs[k]), W2[k*192 + tid], acc);
        float2 f = unpk(acc);
        ((float2*)(g_qkvn + row*384))[tid] = f;
    }
}

// ================= k_attn1 : fused edge-qkv GEMM + dots + v + softmax + AV =================
// grid 512 (b*N+i), 256 threads. Register epilogue (no qkvs staging).
// smem (floats):
//  Ws    [0,32768)            Wqkv_e 64x512
//  ed    [32768,33792)        ull[64][8]
//  dots  [33792,35840)        [8][256]
//  vsm   [35840,52224)        bf16[256][128]
//  qns   [52224,52352)
//  invs  [52352,52360)
//  pav   [52360,52616)        [2][128]
#define A1_SMEM_F 52616
__global__ void __launch_bounds__(256, 1)
k_attn1(const float* __restrict__ e_in, const float* __restrict__ W) {
    extern __shared__ float sm[];
    float* Ws   = sm;
    ull*   Ws2  = (ull*)Ws;
    ull*   ed   = (ull*)(sm + 32768);
    float* dots = sm + 33792;
    __nv_bfloat16* vsm = (__nv_bfloat16*)(sm + 35840);
    float* qns  = sm + 52224;
    float* invs = sm + 52352;
    float* pav  = sm + 52360;

    int bi = blockIdx.x, b = bi >> 8, tid = threadIdx.x;

    {   // weights 8192 float4 / 256 threads
        const float4* Wg = (const float4*)W;
        float4* Wd = (float4*)Ws;
#pragma unroll
        for (int it = 0; it < 32; it++) Wd[tid + it*256] = Wg[tid + it*256];
    }
    if (tid < 128) qns[tid] = g_qkvn[bi*384 + (tid>>4)*48 + (tid&15)];

    int sj = tid >> 6, skk = tid & 63;   // staging map (2 vals/thread)
    float r0 = e_in[((size_t)bi*NN + sj)*DE + skk];
    float r1 = e_in[((size_t)bi*NN + 4 + sj)*DE + skk];
    __syncthreads();

    int lane = tid & 31;
    int h = tid >> 5;                    // warp = head (GEMM cols h*64..h*64+63)
    int rrole = lane >> 3;               // 0:eq 1:ek 2:ev 3:em
    int dd = (lane & 7) * 2;             // d, d+1
    float2 qn2 = ((const float2*)qns)[h*8 + (lane & 7)];

    for (int j0 = 0; j0 < NN; j0 += 8) {
        ed[skk*8 + sj]     = dup2f(r0);
        ed[skk*8 + 4 + sj] = dup2f(r1);
        __syncthreads();
        if (j0 + 8 < NN) {
            r0 = e_in[((size_t)bi*NN + (j0+8+sj))*DE + skk];
            r1 = e_in[((size_t)bi*NN + (j0+12+sj))*DE + skk];
        }
        // GEMM: thread = column pair (tid), 8 j accumulators
        ull acc[8];
#pragma unroll
        for (int q = 0; q < 8; q++) acc[q] = 0ull;
#pragma unroll
        for (int k = 0; k < 64; k++) {
            ull w = Ws2[k*256 + tid];
            ulonglong2 ea = *(const ulonglong2*)(ed + k*8);
            ulonglong2 eb = *(const ulonglong2*)(ed + k*8 + 2);
            ulonglong2 ec = *(const ulonglong2*)(ed + k*8 + 4);
            ulonglong2 eD = *(const ulonglong2*)(ed + k*8 + 6);
            acc[0] = fma2(ea.x, w, acc[0]); acc[1] = fma2(ea.y, w, acc[1]);
            acc[2] = fma2(eb.x, w, acc[2]); acc[3] = fma2(eb.y, w, acc[3]);
            acc[4] = fma2(ec.x, w, acc[4]); acc[5] = fma2(ec.y, w, acc[5]);
            acc[6] = fma2(eD.x, w, acc[6]); acc[7] = fma2(eD.y, w, acc[7]);
        }
        // register epilogue: warp h holds head h's eq/ek/ev/em in lane groups
#pragma unroll
        for (int jj = 0; jj < 8; jj++) {
            int j = j0 + jj;
            float2 a2 = unpk(acc[jj]);
            ull pu = __shfl_sync(0xffffffffu, acc[jj], (lane + 8) & 31);
            float2 part = unpk(pu);          // ek (lanes 0-7) / em (lanes 16-23)
            const float* base = g_qkvn + (size_t)(b*NN + j)*384 + h*48 + dd;
            float2 kn2 = {0.f, 0.f}, vn2 = {0.f, 0.f};
            if (rrole == 0) kn2 = *(const float2*)(base + 16);
            if (rrole == 2) vn2 = *(const float2*)(base + 32);
            float s = (qn2.x + a2.x) * (kn2.x + part.x)
                    + (qn2.y + a2.y) * (kn2.y + part.y);
            s += __shfl_xor_sync(0xffffffffu, s, 4);
            s += __shfl_xor_sync(0xffffffffu, s, 2);
            s += __shfl_xor_sync(0xffffffffu, s, 1);
            if (lane == 0) dots[h*256 + j] = s * SCALE;
            if (rrole == 2) {
                __nv_bfloat162 v2;
                v2.x = __float2bfloat16(vn2.x * part.x + a2.x);
                v2.y = __float2bfloat16(vn2.y * part.y + a2.y);
                *(__nv_bfloat162*)(vsm + j*128 + h*16 + dd) = v2;
            }
        }
        __syncthreads();
    }

    // softmax: warp w = head w
    {
        float* dr = dots + h*256;
        float vr[8]; float m = -1e30f;
#pragma unroll
        for (int q = 0; q < 8; q++) { vr[q] = dr[q*32 + lane]; m = fmaxf(m, vr[q]); }
#pragma unroll
        for (int o = 16; o; o >>= 1) m = fmaxf(m, __shfl_xor_sync(0xffffffffu, m, o));
        float s = 0.f;
#pragma unroll
        for (int q = 0; q < 8; q++) { float p = __expf(vr[q] - m); dr[q*32 + lane] = p; s += p; }
#pragma unroll
        for (int o = 16; o; o >>= 1) s += __shfl_xor_sync(0xffffffffu, s, o);
        if (lane == 0) invs[h] = 1.f/s;
    }
    __syncthreads();

    // AV: thread (hd, half), 128 j each
    {
        int hd = tid & 127, hh = hd >> 4;
        int half = tid >> 7;
        const float* pr = dots + hh*256 + half*128;
        const __nv_bfloat16* vp = vsm + (size_t)half*128*128 + hd;
        float acc = 0.f;
#pragma unroll 8
        for (int jj = 0; jj < 128; jj++)
            acc += pr[jj] * __bfloat162float(vp[jj*128]);
        pav[half*128 + hd] = acc;
    }
    __syncthreads();
    if (tid < 128)
        g_ao[bi*128 + tid] = (pav[tid] + pav[128 + tid]) * invs[tid>>4];
}

// ---------------- k_attn2 : Wo + Wl0 + LN + node MLP + LN (FFMA2, 256 thr) ----------------
__global__ void __launch_bounds__(256)
k_attn2(const float* __restrict__ Wo, const float* __restrict__ bo,
        const float* __restrict__ Wl0, const float* __restrict__ bl0,
        const float* __restrict__ g0, const float* __restrict__ b0,
        const float* __restrict__ Wm1, const float* __restrict__ Wm2,
        const float* __restrict__ bm2,
        const float* __restrict__ g1, const float* __restrict__ b1) {
    __shared__ float outs[DH];
    __shared__ float asv[DH];
    __shared__ float xs[DN];
    __shared__ float hid[DNH];
    __shared__ ull psum[256];    // [4][64]
    __shared__ float red[8];

    int bi = blockIdx.x, tid = threadIdx.x;
    int c2 = tid & 63, ks = tid >> 6;
    int pr2 = tid >> 1, sel = tid & 1;
    int w = tid >> 5;

    if (tid < 128) outs[tid] = g_ao[bi*128 + tid];
    __syncthreads();

    // ao = outs @ Wo (+bo)
    {
        const ull* W2 = (const ull*)Wo;
        ull acc = 0ull;
#pragma unroll 8
        for (int kk = 0; kk < 32; kk++) {
            int k = ks*32 + kk;
            acc = fma2(dup2f(outs[k]), W2[k*64 + c2], acc);
        }
        psum[ks*64 + c2] = acc;
    }
    __syncthreads();
    if (tid < 128) {
        float v = 0.f;
#pragma unroll
        for (int t = 0; t < 4; t++) { float2 f = unpk(psum[t*64 + pr2]); v += sel ? f.y : f.x; }
        asv[tid] = v + bo[tid];
    }
    __syncthreads();

    // y = asv @ Wl0 (+bl0), xv = x + y
    {
        const ull* W2 = (const ull*)Wl0;
        ull acc = 0ull;
#pragma unroll 8
        for (int kk = 0; kk < 32; kk++) {
            int k = ks*32 + kk;
            acc = fma2(dup2f(asv[k]), W2[k*64 + c2], acc);
        }
        psum[ks*64 + c2] = acc;
    }
    __syncthreads();
    float xv = 0.f;
    if (tid < 128) {
        float v = 0.f;
#pragma unroll
        for (int t = 0; t < 4; t++) { float2 f = unpk(psum[t*64 + pr2]); v += sel ? f.y : f.x; }
        xv = g_x[bi*128 + tid] + v + bl0[tid];
        float s1 = xv, s2 = xv*xv;
#pragma unroll
        for (int o = 16; o; o >>= 1) { s1 += __shfl_xor_sync(0xffffffffu, s1, o); s2 += __shfl_xor_sync(0xffffffffu, s2, o); }
        if ((tid & 31) == 0) { red[w*2] = s1; red[w*2+1] = s2; }
    }
    __syncthreads();
    if (tid < 128) {
        float s1 = red[0]+red[2]+red[4]+red[6];
        float s2 = red[1]+red[3]+red[5]+red[7];
        float mean = s1 * (1.0f/DN);
        float var  = s2 * (1.0f/DN) - mean*mean;
        xs[tid] = (xv - mean) * rsqrtf(var + 1e-5f) * g0[tid] + b0[tid];
    }
    __syncthreads();

    // hid = gelu(x1 @ Wm1): thread = ull col (256)
    {
        const ull* W2 = (const ull*)Wm1;
        ull acc = 0ull;
#pragma unroll 8
        for (int k = 0; k < 128; k++)
            acc = fma2(dup2f(xs[k]), W2[k*256 + tid], acc);
        float2 f = unpk(acc);
        hid[2*tid]   = gelu_f(f.x);
        hid[2*tid+1] = gelu_f(f.y);
    }
    __syncthreads();

    // o2 = hid @ Wm2 (+bm2): k=512, 4-way split
    {
        const ull* W2 = (const ull*)Wm2;
        ull acc = 0ull;
#pragma unroll 8
        for (int kk = 0; kk < 128; kk++) {
            int k = ks*128 + kk;
            acc = fma2(dup2f(hid[k]), W2[k*64 + c2], acc);
        }
        psum[ks*64 + c2] = acc;
    }
    __syncthreads();
    float x2 = 0.f;
    if (tid < 128) {
        float v = 0.f;
#pragma unroll
        for (int t = 0; t < 4; t++) { float2 f = unpk(psum[t*64 + pr2]); v += sel ? f.y : f.x; }
        x2 = xs[tid] + v + bm2[tid];
        float s1 = x2, s2 = x2*x2;
#pragma unroll
        for (int o = 16; o; o >>= 1) { s1 += __shfl_xor_sync(0xffffffffu, s1, o); s2 += __shfl_xor_sync(0xffffffffu, s2, o); }
        if ((tid & 31) == 0) { red[w*2] = s1; red[w*2+1] = s2; }
    }
    __syncthreads();
    if (tid < 128) {
        float s1 = red[0]+red[2]+red[4]+red[6];
        float s2 = red[1]+red[3]+red[5]+red[7];
        float mean = s1 * (1.0f/DN);
        float var  = s2 * (1.0f/DN) - mean*mean;
        g_x[bi*128 + tid] = (x2 - mean) * rsqrtf(var + 1e-5f) * g1[tid] + b1[tid];
    }
}

// ---------------- k_srctgt : FFMA2 ----------------
__global__ void __launch_bounds__(256)
k_srctgt(const float* __restrict__ Wsm, const float* __restrict__ bsv,
         const float* __restrict__ Wtm, const float* __restrict__ btv) {
    __shared__ float xs[DN];
    int row = blockIdx.x, tid = threadIdx.x;
    if (tid < 128) xs[tid] = g_x[row*DN + tid];
    __syncthreads();
    int cc = tid & 127;
    bool isT = tid >= 128;
    const ull* W2 = (const ull*)(isT ? Wtm : Wsm);
    ull acc = 0ull;
#pragma unroll 8
    for (int k = 0; k < 128; k++)
        acc = fma2(dup2f(xs[k]), W2[k*128 + cc], acc);
    float2 f = unpk(acc);
    const float2* bv = (const float2*)(isT ? btv : bsv);
    float2 b2 = bv[cc];
    float* dst = isT ? g_t : g_s;
    float2 o2 = { f.x + b2.x, f.y + b2.y };
    ((float2*)(dst + row*DEH))[cc] = o2;
}

// ================= k_e1 : fused edge MLP1 + residual + LN (256 threads, R12) =================
// smem (floats):
//  W0s   [0,32768)        We0 128x256
//  W1s   [32768,49152)    We1 256x64
//  ecatd [49152,51200)    ull[128][8]
//  hiddp [51200,55552)    ull[128][17]
//  psum  [55552,57600)    ull[4][8][32]
//  srcs  [57600,57856)
#define E1_SMEM_F 57856
__global__ void __launch_bounds__(256, 1)
k_e1(const float* __restrict__ e_in, float* __restrict__ e_out,
     const float* __restrict__ We0, const float* __restrict__ be0,
     const float* __restrict__ We1, const float* __restrict__ be1,
     const float* __restrict__ g0, const float* __restrict__ b0) {
    extern __shared__ float sm[];
    float* W0s = sm;          ull* W0s2 = (ull*)W0s;
    float* W1s = sm + 32768;  ull* W1s2 = (ull*)W1s;
    ull* ecatd = (ull*)(sm + 49152);
    ull* hiddp = (ull*)(sm + 51200);
    ull* psum  = (ull*)(sm + 55552);
    float* srcs = sm + 57600;

    int bi = blockIdx.x, b = bi >> 8, i = bi & 255, tid = threadIdx.x;

    {
        const float4* w0 = (const float4*)We0; float4* d0 = (float4*)W0s;
#pragma unroll
        for (int it = 0; it < 32; it++) d0[tid + it*256] = w0[tid + it*256];
        const float4* w1 = (const float4*)We1; float4* d1 = (float4*)W1s;
#pragma unroll
        for (int it = 0; it < 16; it++) d1[tid + it*256] = w1[tid + it*256];
    }
    srcs[tid] = g_s[bi*DEH + tid] + be0[tid];

    // staging map: 1024 vals = 4/thread
    float rv[4];
#pragma unroll
    for (int it = 0; it < 4; it++) {
        int idx = tid + it*256, j = idx >> 7, kk = idx & 127;
        rv[it] = (kk < 64) ? e_in[((size_t)bi*NN + j)*DE + kk]
                           : e_in[(((size_t)b*NN + j)*NN + i)*DE + (kk - 64)];
    }
    __syncthreads();

    int cp1 = tid & 127, jgx = tid >> 7;                 // phase1
    int c2p = tid & 31, jgx2 = (tid >> 5) & 1, ks = tid >> 6;  // phase2
    int jc = tid >> 5, cpc = tid & 31;                   // combine

    for (int j0 = 0; j0 < NN; j0 += 8) {
#pragma unroll
        for (int it = 0; it < 4; it++) {
            int idx = tid + it*256, j = idx >> 7, kk = idx & 127;
            ecatd[kk*8 + j] = dup2f(rv[it]);
        }
        __syncthreads();
        if (j0 + 8 < NN) {
#pragma unroll
            for (int it = 0; it < 4; it++) {
                int idx = tid + it*256, j = (idx >> 7) + j0 + 8, kk = idx & 127;
                rv[it] = (kk < 64) ? e_in[((size_t)bi*NN + j)*DE + kk]
                                   : e_in[(((size_t)b*NN + j)*NN + i)*DE + (kk - 64)];
            }
        }
        // phase1: thread = hid col pair cp1, 4 j
        ull acc[4];
        {
            float2 sv = ((const float2*)srcs)[cp1];
#pragma unroll
            for (int jj = 0; jj < 4; jj++) {
                int j = j0 + jgx*4 + jj;
                float2 tv = ((const float2*)(g_t + (size_t)(b*NN + j)*DEH))[cp1];
                float2 in2 = { sv.x + tv.x, sv.y + tv.y };
                acc[jj] = *(const ull*)&in2;
            }
        }
#pragma unroll
        for (int k = 0; k < 128; k++) {
            ull w = W0s2[k*128 + cp1];
            ulonglong2 ea = *(const ulonglong2*)(ecatd + k*8 + jgx*4);
            ulonglong2 eb = *(const ulonglong2*)(ecatd + k*8 + jgx*4 + 2);
            acc[0] = fma2(ea.x, w, acc[0]);
            acc[1] = fma2(ea.y, w, acc[1]);
            acc[2] = fma2(eb.x, w, acc[2]);
            acc[3] = fma2(eb.y, w, acc[3]);
        }
#pragma unroll
        for (int jj = 0; jj < 4; jj++) {
            float2 f = unpk(acc[jj]);
            int j = jgx*4 + jj;
            hiddp[cp1*17 + j*2 + 0] = dup2f(gelu_f(f.x));
            hiddp[cp1*17 + j*2 + 1] = dup2f(gelu_f(f.y));
        }
        __syncthreads();

        // phase2: out col pair c2p, 4 j, k-split 4
        {
            ull p0=0, p1=0, p2=0, p3=0;
            int kb = ks*64;
#pragma unroll
            for (int kk = 0; kk < 64; kk++) {
                int k = kb + kk;
                ull w = W1s2[k*32 + c2p];
                const ull* hp = hiddp + (k>>1)*17 + (k&1) + jgx2*8;
                p0 = fma2(hp[0], w, p0);
                p1 = fma2(hp[2], w, p1);
                p2 = fma2(hp[4], w, p2);
                p3 = fma2(hp[6], w, p3);
            }
            int jb = jgx2*4;
            psum[(ks*8 + jb+0)*32 + c2p] = p0;
            psum[(ks*8 + jb+1)*32 + c2p] = p1;
            psum[(ks*8 + jb+2)*32 + c2p] = p2;
            psum[(ks*8 + jb+3)*32 + c2p] = p3;
        }
        __syncthreads();

        // combine + residual + LN: warp = one j (32 col pairs)
        {
            float2 q0 = unpk(psum[(0*8 + jc)*32 + cpc]);
            float2 q1 = unpk(psum[(1*8 + jc)*32 + cpc]);
            float2 q2 = unpk(psum[(2*8 + jc)*32 + cpc]);
            float2 q3 = unpk(psum[(3*8 + jc)*32 + cpc]);
            float2 bia = ((const float2*)be1)[cpc];
            float2 res = ((const float2*)(e_in + ((size_t)bi*NN + j0 + jc)*DE))[cpc];
            float r0 = q0.x + q1.x + q2.x + q3.x + bia.x + res.x;
            float r1 = q0.y + q1.y + q2.y + q3.y + bia.y + res.y;
            float s1 = r0 + r1, s2 = r0*r0 + r1*r1;
#pragma unroll
            for (int o = 16; o; o >>= 1) {
                s1 += __shfl_xor_sync(0xffffffffu, s1, o);
                s2 += __shfl_xor_sync(0xffffffffu, s2, o);
            }
            float mean = s1 * (1.f/DE);
            float var  = s2 * (1.f/DE) - mean*mean;
            float rs = rsqrtf(var + 1e-5f);
            float2 gg = ((const float2*)g0)[cpc];
            float2 bb = ((const float2*)b0)[cpc];
            float2 o2 = { (r0 - mean)*rs*gg.x + bb.x, (r1 - mean)*rs*gg.y + bb.y };
            ((float2*)(e_out + ((size_t)bi*NN + j0 + jc)*DE))[cpc] = o2;
        }
        __syncthreads();
    }
}

// ================= k_e2 : fused edge MLP2 + residual + LN, in place (256 threads, R12) =================
// smem (floats):
//  W1s   [0,16384)       Wem1 64x256
//  W2s   [16384,32768)   Wem2 256x64
//  ed    [32768,33792)   ull[64][8]
//  hiddp [33792,38144)   ull[128][17]
//  psum  [38144,40192)   ull[4][8][32]
#define E2_SMEM_F 40192
__global__ void __launch_bounds__(256, 1)
k_e2(float* __restrict__ e_io,
     const float* __restrict__ Wem1, const float* __restrict__ Wem2,
     const float* __restrict__ bem2,
     const float* __restrict__ g1, const float* __restrict__ b1) {
    extern __shared__ float sm[];
    float* W1s = sm;          ull* W1s2 = (ull*)W1s;
    float* W2s = sm + 16384;  ull* W2s2 = (ull*)W2s;
    ull* ed    = (ull*)(sm + 32768);
    ull* hiddp = (ull*)(sm + 33792);
    ull* psum  = (ull*)(sm + 38144);

    int bi = blockIdx.x, tid = threadIdx.x;
    {
        const float4* w1 = (const float4*)Wem1; float4* d1 = (float4*)W1s;
#pragma unroll
        for (int it = 0; it < 16; it++) d1[tid + it*256] = w1[tid + it*256];
        const float4* w2 = (const float4*)Wem2; float4* d2 = (float4*)W2s;
#pragma unroll
        for (int it = 0; it < 16; it++) d2[tid + it*256] = w2[tid + it*256];
    }
    int sj = tid >> 6, skk = tid & 63;
    float r0 = e_io[((size_t)bi*NN + sj)*DE + skk];
    float r1 = e_io[((size_t)bi*NN + 4 + sj)*DE + skk];
    __syncthreads();

    int cp1 = tid & 127, jgx = tid >> 7;
    int c2p = tid & 31, jgx2 = (tid >> 5) & 1, ks = tid >> 6;
    int jc = tid >> 5, cpc = tid & 31;

    for (int j0 = 0; j0 < NN; j0 += 8) {
        ed[skk*8 + sj]     = dup2f(r0);
        ed[skk*8 + 4 + sj] = dup2f(r1);
        __syncthreads();
        if (j0 + 8 < NN) {
            r0 = e_io[((size_t)bi*NN + (j0+8+sj))*DE + skk];
            r1 = e_io[((size_t)bi*NN + (j0+12+sj))*DE + skk];
        }
        // phase1: k=64
        {
            ull acc[4] = {0ull, 0ull, 0ull, 0ull};
#pragma unroll
            for (int k = 0; k < 64; k++) {
                ull w = W1s2[k*128 + cp1];
                ulonglong2 ea = *(const ulonglong2*)(ed + k*8 + jgx*4);
                ulonglong2 eb = *(const ulonglong2*)(ed + k*8 + jgx*4 + 2);
                acc[0] = fma2(ea.x, w, acc[0]);
                acc[1] = fma2(ea.y, w, acc[1]);
                acc[2] = fma2(eb.x, w, acc[2]);
                acc[3] = fma2(eb.y, w, acc[3]);
            }
#pragma unroll
            for (int jj = 0; jj < 4; jj++) {
                float2 f = unpk(acc[jj]);
                int j = jgx*4 + jj;
                hiddp[cp1*17 + j*2 + 0] = dup2f(gelu_f(f.x));
                hiddp[cp1*17 + j*2 + 1] = dup2f(gelu_f(f.y));
            }
        }
        __syncthreads();

        // phase2: k=256, 4-way k split
        {
            ull p0=0, p1=0, p2=0, p3=0;
            int kb = ks*64;
#pragma unroll
            for (int kk = 0; kk < 64; kk++) {
                int k = kb + kk;
                ull w = W2s2[k*32 + c2p];
                const ull* hp = hiddp + (k>>1)*17 + (k&1) + jgx2*8;
                p0 = fma2(hp[0], w, p0);
                p1 = fma2(hp[2], w, p1);
                p2 = fma2(hp[4], w, p2);
                p3 = fma2(hp[6], w, p3);
            }
            int jb = jgx2*4;
            psum[(ks*8 + jb+0)*32 + c2p] = p0;
            psum[(ks*8 + jb+1)*32 + c2p] = p1;
            psum[(ks*8 + jb+2)*32 + c2p] = p2;
            psum[(ks*8 + jb+3)*32 + c2p] = p3;
        }
        __syncthreads();

        // combine + residual + LN
        {
            float2 q0 = unpk(psum[(0*8 + jc)*32 + cpc]);
            float2 q1 = unpk(psum[(1*8 + jc)*32 + cpc]);
            float2 q2 = unpk(psum[(2*8 + jc)*32 + cpc]);
            float2 q3 = unpk(psum[(3*8 + jc)*32 + cpc]);
            float2 bia = ((const float2*)bem2)[cpc];
            float2 res = ((const float2*)(e_io + ((size_t)bi*NN + j0 + jc)*DE))[cpc];
            float r0c = q0.x + q1.x + q2.x + q3.x + bia.x + res.x;
            float r1c = q0.y + q1.y + q2.y + q3.y + bia.y + res.y;
            float s1 = r0c + r1c, s2 = r0c*r0c + r1c*r1c;
#pragma unroll
            for (int o = 16; o; o >>= 1) {
                s1 += __shfl_xor_sync(0xffffffffu, s1, o);
                s2 += __shfl_xor_sync(0xffffffffu, s2, o);
            }
            float mean = s1 * (1.f/DE);
            float var  = s2 * (1.f/DE) - mean*mean;
            float rs = rsqrtf(var + 1e-5f);
            float2 gg = ((const float2*)g1)[cpc];
            float2 bb = ((const float2*)b1)[cpc];
            float2 o2 = { (r0c - mean)*rs*gg.x + bb.x, (r1c - mean)*rs*gg.y + bb.y };
            ((float2*)(e_io + ((size_t)bi*NN + j0 + jc)*DE))[cpc] = o2;
        }
        __syncthreads();
    }
}

// ---------------- k_final ----------------
__global__ void k_final(float* __restrict__ out) {
    int idx = blockIdx.x * blockDim.x + threadIdx.x;
    const int nx = BB*NN*DN;
    const int ne = BB*NN*NN*DE;
    if (idx < nx) out[idx] = g_x[idx];
    else if (idx < nx + ne) out[idx] = g_ebuf0[idx - nx];
}

// ---------------- launch ----------------
extern "C" void kernel_launch(void* const* d_in, const int* in_sizes, int n_in,
                              void* d_out, int out_size) {
    const float* node    = (const float*)d_in[0];
    const float* edge    = (const float*)d_in[1];
    const float* Wqkv_n  = (const float*)d_in[2];
    const float* Wqkv_e  = (const float*)d_in[3];
    const float* Wo      = (const float*)d_in[4];
    const float* bo      = (const float*)d_in[5];
    const float* Wl0     = (const float*)d_in[6];
    const float* bl0     = (const float*)d_in[7];
    const float* ln0_g   = (const float*)d_in[8];
    const float* ln0_b   = (const float*)d_in[9];
    const float* Wm1     = (const float*)d_in[10];
    const float* Wm2     = (const float*)d_in[11];
    const float* bm2     = (const float*)d_in[12];
    const float* ln1_g   = (const float*)d_in[13];
    const float* ln1_b   = (const float*)d_in[14];
    const float* We0     = (const float*)d_in[15];
    const float* be0     = (const float*)d_in[16];
    const float* Wsm     = (const float*)d_in[17];
    const float* bsv     = (const float*)d_in[18];
    const float* Wtm     = (const float*)d_in[19];
    const float* btv     = (const float*)d_in[20];
    const float* We1     = (const float*)d_in[21];
    const float* be1     = (const float*)d_in[22];
    const float* eln0_g  = (const float*)d_in[23];
    const float* eln0_b  = (const float*)d_in[24];
    const float* Wem1    = (const float*)d_in[25];
    const float* Wem2    = (const float*)d_in[26];
    const float* bem2    = (const float*)d_in[27];
    const float* eln1_g  = (const float*)d_in[28];
    const float* eln1_b  = (const float*)d_in[29];
    float* out = (float*)d_out;

    cudaFuncSetAttribute(k_attn1, cudaFuncAttributeMaxDynamicSharedMemorySize, A1_SMEM_F*4);
    cudaFuncSetAttribute(k_e1,    cudaFuncAttributeMaxDynamicSharedMemorySize, E1_SMEM_F*4);
    cudaFuncSetAttribute(k_e2,    cudaFuncAttributeMaxDynamicSharedMemorySize, E2_SMEM_F*4);

    float *pe0, *pe1;
    cudaGetSymbolAddress((void**)&pe0, g_ebuf0);
    cudaGetSymbolAddress((void**)&pe1, g_ebuf1);

    k_copy_x<<<(BB*NN*DN + 255)/256, 256>>>(node);

    const float* e_in = edge;
    float* e_out = pe1;

    for (int l = 0; l < LL; l++) {
        k_qkvn<<<BB*NN, 256>>>(Wqkv_n + (size_t)l*DN*3*DH);
        k_attn1<<<BB*NN, 256, A1_SMEM_F*4>>>(e_in, Wqkv_e + (size_t)l*DE*4*DH);
        k_attn2<<<BB*NN, 256>>>(Wo + (size_t)l*DH*DN, bo + (size_t)l*DN,
                                Wl0 + (size_t)l*DN*DN, bl0 + (size_t)l*DN,
                                ln0_g + (size_t)l*DN, ln0_b + (size_t)l*DN,
                                Wm1 + (size_t)l*DN*DNH, Wm2 + (size_t)l*DNH*DN,
                                bm2 + (size_t)l*DN,
                                ln1_g + (size_t)l*DN, ln1_b + (size_t)l*DN);
        k_srctgt<<<BB*NN, 256>>>(Wsm + (size_t)l*DN*DEH, bsv + (size_t)l*DEH,
                                 Wtm + (size_t)l*DN*DEH, btv + (size_t)l*DEH);
        k_e1<<<BB*NN, 256, E1_SMEM_F*4>>>(e_in, e_out,
                                          We0 + (size_t)l*2*DE*DEH, be0 + (size_t)l*DEH,
                                          We1 + (size_t)l*DEH*DE, be1 + (size_t)l*DE,
                                          eln0_g + (size_t)l*DE, eln0_b + (size_t)l*DE);
        k_e2<<<BB*NN, 256, E2_SMEM_F*4>>>(e_out,
                                          Wem1 + (size_t)l*DE*DEH, Wem2 + (size_t)l*DEH*DE,
                                          bem2 + (size_t)l*DE,
                                          eln1_g + (size_t)l*DE, eln1_b + (size_t)l*DE);
        e_in = e_out;
        e_out = pe0;
    }

    int total = BB*NN*DN + BB*NN*NN*DE;
    k_final<<<(total + 255)/256, 256>>>(out);
}

// round 17
// speedup vs baseline: 1.1865x; 1.1395x over previous
#include <cuda_runtime.h>
#include <cuda_bf16.h>
#include <cstdint>
#include <cstddef>

// ---------------- dims ----------------
#define BB   2
#define NN   256
#define DN   128
#define DE   64
#define DH   128
#define HH   8
#define DHH  16
#define DNH  512
#define DEH  256
#define LL   2

#define SCALE 0.08838834764831845f   // 1/sqrt(128)

typedef unsigned long long ull;

// ---------------- packed f32x2 helpers ----------------
__device__ __forceinline__ ull fma2(ull a, ull b, ull c) {
    ull d;
    asm("fma.rn.f32x2 %0, %1, %2, %3;" : "=l"(d) : "l"(a), "l"(b), "l"(c));
    return d;
}
__device__ __forceinline__ ull dup2f(float x) {
    ull r; asm("mov.b64 %0, {%1, %1};" : "=l"(r) : "f"(x)); return r;
}
__device__ __forceinline__ float2 unpk(ull v) {
    float2 r; asm("mov.b64 {%0, %1}, %2;" : "=f"(r.x), "=f"(r.y) : "l"(v)); return r;
}

__device__ __forceinline__ float gelu_f(float x) {
    return 0.5f * x * (1.0f + erff(x * 0.70710678118654752440f));
}

// ---------------- persistent scratch ----------------
__device__ float g_x[BB*NN*DN];
__device__ float g_qkvn[BB*NN*3*DH];
__device__ float g_ao[BB*NN*DH];
__device__ float g_s[BB*NN*DEH];
__device__ float g_t[BB*NN*DEH];
__device__ float g_ebuf1[(size_t)BB*NN*NN*DE];
__device__ float g_ebuf0[(size_t)BB*NN*NN*DE];

// ---------------- k_copy_x ----------------
__global__ void k_copy_x(const float* __restrict__ node) {
    int i = blockIdx.x * blockDim.x + threadIdx.x;
    if (i < BB*NN*DN) g_x[i] = node[i];
}

// ---------------- k_qkvn (R12: 128 threads, scalar) ----------------
__global__ void k_qkvn(const float* __restrict__ W) {
    __shared__ float xs[DN];
    int row = blockIdx.x, tid = threadIdx.x;
    xs[tid] = g_x[row*DN + tid];
    __syncthreads();
    float a0 = 0.f, a1 = 0.f, a2 = 0.f;
#pragma unroll 8
    for (int k = 0; k < DN; k++) {
        float xv = xs[k];
        const float* w = W + k*384;
        a0 += xv * w[tid];
        a1 += xv * w[tid + 128];
        a2 += xv * w[tid + 256];
    }
    float* o = g_qkvn + row*384;
    o[tid] = a0; o[tid + 128] = a1; o[tid + 256] = a2;
}

// ================= k_attn1 (R12): fused edge-qkv GEMM + dots + v + softmax + AV =================
// grid 512 (b*N+i), 256 threads.
// smem (floats):
//  Ws    [0,32768)            Wqkv_e 64x512
//  ed    [32768,33792)        ull[64][8]
//  qkvs  [33792,37888)        ull[8][256]
//  dots  [37888,39936)        [8][256]
//  vsm   [39936,56320)        bf16[256][128]
//  qns   [56320,56448)
//  invs  [56448,56456)
//  pav   [56456,56712)
#define A1_SMEM_F 56712
__global__ void __launch_bounds__(256, 1)
k_attn1(const float* __restrict__ e_in, const float* __restrict__ W) {
    extern __shared__ float sm[];
    float* Ws   = sm;
    ull*   Ws2  = (ull*)Ws;
    ull*   ed   = (ull*)(sm + 32768);
    float* qkvs = sm + 33792;
    ull*   qkvs2 = (ull*)qkvs;
    float* dots = sm + 37888;
    __nv_bfloat16* vsm = (__nv_bfloat16*)(sm + 39936);
    float* qns  = sm + 56320;
    float* invs = sm + 56448;
    float* pav  = sm + 56456;

    int bi = blockIdx.x, b = bi >> 8, tid = threadIdx.x;

    {   // weights 32768 f
        const float4* Wg = (const float4*)W;
        float4* Wd = (float4*)Ws;
#pragma unroll
        for (int it = 0; it < 32; it++) Wd[tid + it*256] = Wg[tid + it*256];
    }
    if (tid < 128) qns[tid] = g_qkvn[bi*384 + (tid>>4)*48 + (tid&15)];

    int sj = tid >> 6, skk = tid & 63;   // staging map (2 vals/thread)
    float r0 = e_in[((size_t)bi*NN + sj)*DE + skk];
    float r1 = e_in[((size_t)bi*NN + 4 + sj)*DE + skk];
    __syncthreads();

    int hd = tid & 127, jgx = tid >> 7;
    int h = hd >> 4, d = hd & 15;

    for (int j0 = 0; j0 < NN; j0 += 8) {
        ed[skk*8 + sj]     = dup2f(r0);
        ed[skk*8 + 4 + sj] = dup2f(r1);
        __syncthreads();
        if (j0 + 8 < NN) {
            r0 = e_in[((size_t)bi*NN + (j0+8+sj))*DE + skk];
            r1 = e_in[((size_t)bi*NN + (j0+12+sj))*DE + skk];
        }
        // GEMM: thread = column pair (tid of 256), all 8 j
        ull a0=0,a1=0,a2=0,a3=0,a4=0,a5=0,a6=0,a7=0;
#pragma unroll
        for (int k = 0; k < 64; k++) {
            ull w = Ws2[k*256 + tid];
            ulonglong2 ea = *(const ulonglong2*)(ed + k*8);
            ulonglong2 eb = *(const ulonglong2*)(ed + k*8 + 2);
            ulonglong2 ec = *(const ulonglong2*)(ed + k*8 + 4);
            ulonglong2 eD = *(const ulonglong2*)(ed + k*8 + 6);
            a0 = fma2(ea.x, w, a0); a1 = fma2(ea.y, w, a1);
            a2 = fma2(eb.x, w, a2); a3 = fma2(eb.y, w, a3);
            a4 = fma2(ec.x, w, a4); a5 = fma2(eD.x, w, a5);
            a6 = fma2(ec.y, w, a6); a7 = fma2(eD.y, w, a7);
        }
        qkvs2[0*256 + tid] = a0; qkvs2[1*256 + tid] = a1;
        qkvs2[2*256 + tid] = a2; qkvs2[3*256 + tid] = a3;
        qkvs2[4*256 + tid] = a4; qkvs2[6*256 + tid] = a5;
        qkvs2[5*256 + tid] = a6; qkvs2[7*256 + tid] = a7;
        __syncthreads();

        // epilogue: (h,d) x 4 j per thread
        float qn = qns[hd];
#pragma unroll
        for (int jj = 0; jj < 4; jj++) {
            int jr = jgx*4 + jj, j = j0 + jr;
            const float* qv = qkvs + jr*512 + h*64 + d;
            float eq = qv[0], ek = qv[16], ev = qv[32], em = qv[48];
            const float* kv = g_qkvn + (size_t)(b*NN + j)*384 + h*48 + d;
            float kn = kv[16], vn = kv[32];
            float pd = (qn + eq) * (kn + ek);
            pd += __shfl_xor_sync(0xffffffffu, pd, 8);
            pd += __shfl_xor_sync(0xffffffffu, pd, 4);
            pd += __shfl_xor_sync(0xffffffffu, pd, 2);
            pd += __shfl_xor_sync(0xffffffffu, pd, 1);
            if (d == 0) dots[h*256 + j] = pd * SCALE;
            vsm[j*128 + hd] = __float2bfloat16(vn*em + ev);
        }
        __syncthreads();
    }

    // softmax: warp w = head w
    {
        int wid = tid >> 5, lane = tid & 31;
        float* dr = dots + wid*256;
        float vr[8]; float m = -1e30f;
#pragma unroll
        for (int q = 0; q < 8; q++) { vr[q] = dr[q*32 + lane]; m = fmaxf(m, vr[q]); }
#pragma unroll
        for (int o = 16; o; o >>= 1) m = fmaxf(m, __shfl_xor_sync(0xffffffffu, m, o));
        float s = 0.f;
#pragma unroll
        for (int q = 0; q < 8; q++) { float p = __expf(vr[q] - m); dr[q*32 + lane] = p; s += p; }
#pragma unroll
        for (int o = 16; o; o >>= 1) s += __shfl_xor_sync(0xffffffffu, s, o);
        if (lane == 0) invs[wid] = 1.f/s;
    }
    __syncthreads();

    // AV: thread (hd, half), sum over 128 j
    {
        int hd2 = tid & 127, hh = hd2 >> 4;
        int half = tid >> 7;
        const float* pr = dots + hh*256 + half*128;
        const __nv_bfloat16* vp = vsm + (size_t)half*128*128 + hd2;
        float acc = 0.f;
#pragma unroll 8
        for (int jj = 0; jj < 128; jj++)
            acc += pr[jj] * __bfloat162float(vp[jj*128]);
        pav[half*128 + hd2] = acc;
    }
    __syncthreads();
    if (tid < 128)
        g_ao[bi*128 + tid] = (pav[tid] + pav[128 + tid]) * invs[tid>>4];
}

// ---------------- k_attn2 (R15, verified 42us): Wo + Wl0 + LN + node MLP + LN ----------------
__global__ void __launch_bounds__(256)
k_attn2(const float* __restrict__ Wo, const float* __restrict__ bo,
        const float* __restrict__ Wl0, const float* __restrict__ bl0,
        const float* __restrict__ g0, const float* __restrict__ b0,
        const float* __restrict__ Wm1, const float* __restrict__ Wm2,
        const float* __restrict__ bm2,
        const float* __restrict__ g1, const float* __restrict__ b1) {
    __shared__ float outs[DH];
    __shared__ float asv[DH];
    __shared__ float xs[DN];
    __shared__ float hid[DNH];
    __shared__ ull psum[256];    // [4][64]
    __shared__ float red[8];

    int bi = blockIdx.x, tid = threadIdx.x;
    int c2 = tid & 63, ks = tid >> 6;
    int pr2 = tid >> 1, sel = tid & 1;
    int w = tid >> 5;

    if (tid < 128) outs[tid] = g_ao[bi*128 + tid];
    __syncthreads();

    // ao = outs @ Wo (+bo)
    {
        const ull* W2 = (const ull*)Wo;
        ull acc = 0ull;
#pragma unroll 8
        for (int kk = 0; kk < 32; kk++) {
            int k = ks*32 + kk;
            acc = fma2(dup2f(outs[k]), W2[k*64 + c2], acc);
        }
        psum[ks*64 + c2] = acc;
    }
    __syncthreads();
    if (tid < 128) {
        float v = 0.f;
#pragma unroll
        for (int t = 0; t < 4; t++) { float2 f = unpk(psum[t*64 + pr2]); v += sel ? f.y : f.x; }
        asv[tid] = v + bo[tid];
    }
    __syncthreads();

    // y = asv @ Wl0 (+bl0), xv = x + y
    {
        const ull* W2 = (const ull*)Wl0;
        ull acc = 0ull;
#pragma unroll 8
        for (int kk = 0; kk < 32; kk++) {
            int k = ks*32 + kk;
            acc = fma2(dup2f(asv[k]), W2[k*64 + c2], acc);
        }
        psum[ks*64 + c2] = acc;
    }
    __syncthreads();
    float xv = 0.f;
    if (tid < 128) {
        float v = 0.f;
#pragma unroll
        for (int t = 0; t < 4; t++) { float2 f = unpk(psum[t*64 + pr2]); v += sel ? f.y : f.x; }
        xv = g_x[bi*128 + tid] + v + bl0[tid];
        float s1 = xv, s2 = xv*xv;
#pragma unroll
        for (int o = 16; o; o >>= 1) { s1 += __shfl_xor_sync(0xffffffffu, s1, o); s2 += __shfl_xor_sync(0xffffffffu, s2, o); }
        if ((tid & 31) == 0) { red[w*2] = s1; red[w*2+1] = s2; }
    }
    __syncthreads();
    if (tid < 128) {
        float s1 = red[0]+red[2]+red[4]+red[6];
        float s2 = red[1]+red[3]+red[5]+red[7];
        float mean = s1 * (1.0f/DN);
        float var  = s2 * (1.0f/DN) - mean*mean;
        xs[tid] = (xv - mean) * rsqrtf(var + 1e-5f) * g0[tid] + b0[tid];
    }
    __syncthreads();

    // hid = gelu(x1 @ Wm1): thread = ull col (256)
    {
        const ull* W2 = (const ull*)Wm1;
        ull acc = 0ull;
#pragma unroll 8
        for (int k = 0; k < 128; k++)
            acc = fma2(dup2f(xs[k]), W2[k*256 + tid], acc);
        float2 f = unpk(acc);
        hid[2*tid]   = gelu_f(f.x);
        hid[2*tid+1] = gelu_f(f.y);
    }
    __syncthreads();

    // o2 = hid @ Wm2 (+bm2): k=512, 4-way split
    {
        const ull* W2 = (const ull*)Wm2;
        ull acc = 0ull;
#pragma unroll 8
        for (int kk = 0; kk < 128; kk++) {
            int k = ks*128 + kk;
            acc = fma2(dup2f(hid[k]), W2[k*64 + c2], acc);
        }
        psum[ks*64 + c2] = acc;
    }
    __syncthreads();
    float x2 = 0.f;
    if (tid < 128) {
        float v = 0.f;
#pragma unroll
        for (int t = 0; t < 4; t++) { float2 f = unpk(psum[t*64 + pr2]); v += sel ? f.y : f.x; }
        x2 = xs[tid] + v + bm2[tid];
        float s1 = x2, s2 = x2*x2;
#pragma unroll
        for (int o = 16; o; o >>= 1) { s1 += __shfl_xor_sync(0xffffffffu, s1, o); s2 += __shfl_xor_sync(0xffffffffu, s2, o); }
        if ((tid & 31) == 0) { red[w*2] = s1; red[w*2+1] = s2; }
    }
    __syncthreads();
    if (tid < 128) {
        float s1 = red[0]+red[2]+red[4]+red[6];
        float s2 = red[1]+red[3]+red[5]+red[7];
        float mean = s1 * (1.0f/DN);
        float var  = s2 * (1.0f/DN) - mean*mean;
        g_x[bi*128 + tid] = (x2 - mean) * rsqrtf(var + 1e-5f) * g1[tid] + b1[tid];
    }
}

// ---------------- k_srctgt (R12: scalar, 256 threads) ----------------
__global__ void __launch_bounds__(256)
k_srctgt(const float* __restrict__ Wsm, const float* __restrict__ bsv,
         const float* __restrict__ Wtm, const float* __restrict__ btv) {
    __shared__ float xs[DN];
    int row = blockIdx.x, tid = threadIdx.x;
    if (tid < DN) xs[tid] = g_x[row*DN + tid];
    __syncthreads();
    float s = bsv[tid], t = btv[tid];
#pragma unroll 4
    for (int k = 0; k < DN; k++) {
        float xv = xs[k];
        s += xv * Wsm[k*DEH + tid];
        t += xv * Wtm[k*DEH + tid];
    }
    g_s[row*DEH + tid] = s;
    g_t[row*DEH + tid] = t;
}

// ================= k_e1 (R12): fused edge MLP1 + residual + LN =================
// smem (floats):
//  W0s   [0,32768)        We0 128x256
//  W1s   [32768,49152)    We1 256x64
//  ecatd [49152,51200)    ull[128][8]
//  hiddp [51200,55552)    ull[128][17]
//  psum  [55552,57600)    ull[4][8][32]
//  srcs  [57600,57856)
#define E1_SMEM_F 57856
__global__ void __launch_bounds__(256, 1)
k_e1(const float* __restrict__ e_in, float* __restrict__ e_out,
     const float* __restrict__ We0, const float* __restrict__ be0,
     const float* __restrict__ We1, const float* __restrict__ be1,
     const float* __restrict__ g0, const float* __restrict__ b0) {
    extern __shared__ float sm[];
    float* W0s = sm;          ull* W0s2 = (ull*)W0s;
    float* W1s = sm + 32768;  ull* W1s2 = (ull*)W1s;
    ull* ecatd = (ull*)(sm + 49152);
    ull* hiddp = (ull*)(sm + 51200);
    ull* psum  = (ull*)(sm + 55552);
    float* srcs = sm + 57600;

    int bi = blockIdx.x, b = bi >> 8, i = bi & 255, tid = threadIdx.x;

    {
        const float4* w0 = (const float4*)We0; float4* d0 = (float4*)W0s;
#pragma unroll
        for (int it = 0; it < 32; it++) d0[tid + it*256] = w0[tid + it*256];
        const float4* w1 = (const float4*)We1; float4* d1 = (float4*)W1s;
#pragma unroll
        for (int it = 0; it < 16; it++) d1[tid + it*256] = w1[tid + it*256];
    }
    srcs[tid] = g_s[bi*DEH + tid] + be0[tid];

    // staging map: 1024 vals = 4/thread
    float rv[4];
#pragma unroll
    for (int it = 0; it < 4; it++) {
        int idx = tid + it*256, j = idx >> 7, kk = idx & 127;
        rv[it] = (kk < 64) ? e_in[((size_t)bi*NN + j)*DE + kk]
                           : e_in[(((size_t)b*NN + j)*NN + i)*DE + (kk - 64)];
    }
    __syncthreads();

    int cp1 = tid & 127, jgx = tid >> 7;                 // phase1
    int c2p = tid & 31, jgx2 = (tid >> 5) & 1, ks = tid >> 6;  // phase2
    int jc = tid >> 5, cpc = tid & 31;                   // combine

    for (int j0 = 0; j0 < NN; j0 += 8) {
#pragma unroll
        for (int it = 0; it < 4; it++) {
            int idx = tid + it*256, j = idx >> 7, kk = idx & 127;
            ecatd[kk*8 + j] = dup2f(rv[it]);
        }
        __syncthreads();
        if (j0 + 8 < NN) {
#pragma unroll
            for (int it = 0; it < 4; it++) {
                int idx = tid + it*256, j = (idx >> 7) + j0 + 8, kk = idx & 127;
                rv[it] = (kk < 64) ? e_in[((size_t)bi*NN + j)*DE + kk]
                                   : e_in[(((size_t)b*NN + j)*NN + i)*DE + (kk - 64)];
            }
        }
        // phase1: thread = hid col pair cp1, 4 j
        ull acc[4];
        {
            float2 sv = ((const float2*)srcs)[cp1];
#pragma unroll
            for (int jj = 0; jj < 4; jj++) {
                int j = j0 + jgx*4 + jj;
                float2 tv = ((const float2*)(g_t + (size_t)(b*NN + j)*DEH))[cp1];
                float2 in2 = { sv.x + tv.x, sv.y + tv.y };
                acc[jj] = *(const ull*)&in2;
            }
        }
#pragma unroll
        for (int k = 0; k < 128; k++) {
            ull w = W0s2[k*128 + cp1];
            ulonglong2 ea = *(const ulonglong2*)(ecatd + k*8 + jgx*4);
            ulonglong2 eb = *(const ulonglong2*)(ecatd + k*8 + jgx*4 + 2);
            acc[0] = fma2(ea.x, w, acc[0]);
            acc[1] = fma2(ea.y, w, acc[1]);
            acc[2] = fma2(eb.x, w, acc[2]);
            acc[3] = fma2(eb.y, w, acc[3]);
        }
#pragma unroll
        for (int jj = 0; jj < 4; jj++) {
            float2 f = unpk(acc[jj]);
            int j = jgx*4 + jj;
            hiddp[cp1*17 + j*2 + 0] = dup2f(gelu_f(f.x));
            hiddp[cp1*17 + j*2 + 1] = dup2f(gelu_f(f.y));
        }
        __syncthreads();

        // phase2: out col pair c2p, 4 j, k-split 4
        {
            ull p0=0, p1=0, p2=0, p3=0;
            int kb = ks*64;
#pragma unroll
            for (int kk = 0; kk < 64; kk++) {
                int k = kb + kk;
                ull w = W1s2[k*32 + c2p];
                const ull* hp = hiddp + (k>>1)*17 + (k&1) + jgx2*8;
                p0 = fma2(hp[0], w, p0);
                p1 = fma2(hp[2], w, p1);
                p2 = fma2(hp[4], w, p2);
                p3 = fma2(hp[6], w, p3);
            }
            int jb = jgx2*4;
            psum[(ks*8 + jb+0)*32 + c2p] = p0;
            psum[(ks*8 + jb+1)*32 + c2p] = p1;
            psum[(ks*8 + jb+2)*32 + c2p] = p2;
            psum[(ks*8 + jb+3)*32 + c2p] = p3;
        }
        __syncthreads();

        // combine + residual + LN: warp = one j (32 col pairs)
        {
            float2 q0 = unpk(psum[(0*8 + jc)*32 + cpc]);
            float2 q1 = unpk(psum[(1*8 + jc)*32 + cpc]);
            float2 q2 = unpk(psum[(2*8 + jc)*32 + cpc]);
            float2 q3 = unpk(psum[(3*8 + jc)*32 + cpc]);
            float2 bia = ((const float2*)be1)[cpc];
            float2 res = ((const float2*)(e_in + ((size_t)bi*NN + j0 + jc)*DE))[cpc];
            float r0 = q0.x + q1.x + q2.x + q3.x + bia.x + res.x;
            float r1 = q0.y + q1.y + q2.y + q3.y + bia.y + res.y;
            float s1 = r0 + r1, s2 = r0*r0 + r1*r1;
#pragma unroll
            for (int o = 16; o; o >>= 1) {
                s1 += __shfl_xor_sync(0xffffffffu, s1, o);
                s2 += __shfl_xor_sync(0xffffffffu, s2, o);
            }
            float mean = s1 * (1.f/DE);
            float var  = s2 * (1.f/DE) - mean*mean;
            float rs = rsqrtf(var + 1e-5f);
            float2 gg = ((const float2*)g0)[cpc];
            float2 bb = ((const float2*)b0)[cpc];
            float2 o2 = { (r0 - mean)*rs*gg.x + bb.x, (r1 - mean)*rs*gg.y + bb.y };
            ((float2*)(e_out + ((size_t)bi*NN + j0 + jc)*DE))[cpc] = o2;
        }
        __syncthreads();
    }
}

// ================= k_e2 (R12): fused edge MLP2 + residual + LN, in place =================
// smem (floats):
//  W1s   [0,16384)       Wem1 64x256
//  W2s   [16384,32768)   Wem2 256x64
//  ed    [32768,33792)   ull[64][8]
//  hiddp [33792,38144)   ull[128][17]
//  psum  [38144,40192)   ull[4][8][32]
#define E2_SMEM_F 40192
__global__ void __launch_bounds__(256, 1)
k_e2(float* __restrict__ e_io,
     const float* __restrict__ Wem1, const float* __restrict__ Wem2,
     const float* __restrict__ bem2,
     const float* __restrict__ g1, const float* __restrict__ b1) {
    extern __shared__ float sm[];
    float* W1s = sm;          ull* W1s2 = (ull*)W1s;
    float* W2s = sm + 16384;  ull* W2s2 = (ull*)W2s;
    ull* ed    = (ull*)(sm + 32768);
    ull* hiddp = (ull*)(sm + 33792);
    ull* psum  = (ull*)(sm + 38144);

    int bi = blockIdx.x, tid = threadIdx.x;
    {
        const float4* w1 = (const float4*)Wem1; float4* d1 = (float4*)W1s;
#pragma unroll
        for (int it = 0; it < 16; it++) d1[tid + it*256] = w1[tid + it*256];
        const float4* w2 = (const float4*)Wem2; float4* d2 = (float4*)W2s;
#pragma unroll
        for (int it = 0; it < 16; it++) d2[tid + it*256] = w2[tid + it*256];
    }
    int sj = tid >> 6, skk = tid & 63;
    float r0 = e_io[((size_t)bi*NN + sj)*DE + skk];
    float r1 = e_io[((size_t)bi*NN + 4 + sj)*DE + skk];
    __syncthreads();

    int cp1 = tid & 127, jgx = tid >> 7;
    int c2p = tid & 31, jgx2 = (tid >> 5) & 1, ks = tid >> 6;
    int jc = tid >> 5, cpc = tid & 31;

    for (int j0 = 0; j0 < NN; j0 += 8) {
        ed[skk*8 + sj]     = dup2f(r0);
        ed[skk*8 + 4 + sj] = dup2f(r1);
        __syncthreads();
        if (j0 + 8 < NN) {
            r0 = e_io[((size_t)bi*NN + (j0+8+sj))*DE + skk];
            r1 = e_io[((size_t)bi*NN + (j0+12+sj))*DE + skk];
        }
        // phase1: k=64
        {
            ull acc[4] = {0ull, 0ull, 0ull, 0ull};
#pragma unroll
            for (int k = 0; k < 64; k++) {
                ull w = W1s2[k*128 + cp1];
                ulonglong2 ea = *(const ulonglong2*)(ed + k*8 + jgx*4);
                ulonglong2 eb = *(const ulonglong2*)(ed + k*8 + jgx*4 + 2);
                acc[0] = fma2(ea.x, w, acc[0]);
                acc[1] = fma2(ea.y, w, acc[1]);
                acc[2] = fma2(eb.x, w, acc[2]);
                acc[3] = fma2(eb.y, w, acc[3]);
            }
#pragma unroll
            for (int jj = 0; jj < 4; jj++) {
                float2 f = unpk(acc[jj]);
                int j = jgx*4 + jj;
                hiddp[cp1*17 + j*2 + 0] = dup2f(gelu_f(f.x));
                hiddp[cp1*17 + j*2 + 1] = dup2f(gelu_f(f.y));
            }
        }
        __syncthreads();

        // phase2: k=256, 4-way k split
        {
            ull p0=0, p1=0, p2=0, p3=0;
            int kb = ks*64;
#pragma unroll
            for (int kk = 0; kk < 64; kk++) {
                int k = kb + kk;
                ull w = W2s2[k*32 + c2p];
                const ull* hp = hiddp + (k>>1)*17 + (k&1) + jgx2*8;
                p0 = fma2(hp[0], w, p0);
                p1 = fma2(hp[2], w, p1);
                p2 = fma2(hp[4], w, p2);
                p3 = fma2(hp[6], w, p3);
            }
            int jb = jgx2*4;
            psum[(ks*8 + jb+0)*32 + c2p] = p0;
            psum[(ks*8 + jb+1)*32 + c2p] = p1;
            psum[(ks*8 + jb+2)*32 + c2p] = p2;
            psum[(ks*8 + jb+3)*32 + c2p] = p3;
        }
        __syncthreads();

        // combine + residual + LN
        {
            float2 q0 = unpk(psum[(0*8 + jc)*32 + cpc]);
            float2 q1 = unpk(psum[(1*8 + jc)*32 + cpc]);
            float2 q2 = unpk(psum[(2*8 + jc)*32 + cpc]);
            float2 q3 = unpk(psum[(3*8 + jc)*32 + cpc]);
            float2 bia = ((const float2*)bem2)[cpc];
            float2 res = ((const float2*)(e_io + ((size_t)bi*NN + j0 + jc)*DE))[cpc];
            float r0c = q0.x + q1.x + q2.x + q3.x + bia.x + res.x;
            float r1c = q0.y + q1.y + q2.y + q3.y + bia.y + res.y;
            float s1 = r0c + r1c, s2 = r0c*r0c + r1c*r1c;
#pragma unroll
            for (int o = 16; o; o >>= 1) {
                s1 += __shfl_xor_sync(0xffffffffu, s1, o);
                s2 += __shfl_xor_sync(0xffffffffu, s2, o);
            }
            float mean = s1 * (1.f/DE);
            float var  = s2 * (1.f/DE) - mean*mean;
            float rs = rsqrtf(var + 1e-5f);
            float2 gg = ((const float2*)g1)[cpc];
            float2 bb = ((const float2*)b1)[cpc];
            float2 o2 = { (r0c - mean)*rs*gg.x + bb.x, (r1c - mean)*rs*gg.y + bb.y };
            ((float2*)(e_io + ((size_t)bi*NN + j0 + jc)*DE))[cpc] = o2;
        }
        __syncthreads();
    }
}

// ---------------- k_final ----------------
__global__ void k_final(float* __restrict__ out) {
    int idx = blockIdx.x * blockDim.x + threadIdx.x;
    const int nx = BB*NN*DN;
    const int ne = BB*NN*NN*DE;
    if (idx < nx) out[idx] = g_x[idx];
    else if (idx < nx + ne) out[idx] = g_ebuf0[idx - nx];
}

// ---------------- launch ----------------
extern "C" void kernel_launch(void* const* d_in, const int* in_sizes, int n_in,
                              void* d_out, int out_size) {
    const float* node    = (const float*)d_in[0];
    const float* edge    = (const float*)d_in[1];
    const float* Wqkv_n  = (const float*)d_in[2];
    const float* Wqkv_e  = (const float*)d_in[3];
    const float* Wo      = (const float*)d_in[4];
    const float* bo      = (const float*)d_in[5];
    const float* Wl0     = (const float*)d_in[6];
    const float* bl0     = (const float*)d_in[7];
    const float* ln0_g   = (const float*)d_in[8];
    const float* ln0_b   = (const float*)d_in[9];
    const float* Wm1     = (const float*)d_in[10];
    const float* Wm2     = (const float*)d_in[11];
    const float* bm2     = (const float*)d_in[12];
    const float* ln1_g   = (const float*)d_in[13];
    const float* ln1_b   = (const float*)d_in[14];
    const float* We0     = (const float*)d_in[15];
    const float* be0     = (const float*)d_in[16];
    const float* Wsm     = (const float*)d_in[17];
    const float* bsv     = (const float*)d_in[18];
    const float* Wtm     = (const float*)d_in[19];
    const float* btv     = (const float*)d_in[20];
    const float* We1     = (const float*)d_in[21];
    const float* be1     = (const float*)d_in[22];
    const float* eln0_g  = (const float*)d_in[23];
    const float* eln0_b  = (const float*)d_in[24];
    const float* Wem1    = (const float*)d_in[25];
    const float* Wem2    = (const float*)d_in[26];
    const float* bem2    = (const float*)d_in[27];
    const float* eln1_g  = (const float*)d_in[28];
    const float* eln1_b  = (const float*)d_in[29];
    float* out = (float*)d_out;

    cudaFuncSetAttribute(k_attn1, cudaFuncAttributeMaxDynamicSharedMemorySize, A1_SMEM_F*4);
    cudaFuncSetAttribute(k_e1,    cudaFuncAttributeMaxDynamicSharedMemorySize, E1_SMEM_F*4);
    cudaFuncSetAttribute(k_e2,    cudaFuncAttributeMaxDynamicSharedMemorySize, E2_SMEM_F*4);

    float *pe0, *pe1;
    cudaGetSymbolAddress((void**)&pe0, g_ebuf0);
    cudaGetSymbolAddress((void**)&pe1, g_ebuf1);

    k_copy_x<<<(BB*NN*DN + 255)/256, 256>>>(node);

    const float* e_in = edge;
    float* e_out = pe1;

    for (int l = 0; l < LL; l++) {
        k_qkvn<<<BB*NN, 128>>>(Wqkv_n + (size_t)l*DN*3*DH);
        k_attn1<<<BB*NN, 256, A1_SMEM_F*4>>>(e_in, Wqkv_e + (size_t)l*DE*4*DH);
        k_attn2<<<BB*NN, 256>>>(Wo + (size_t)l*DH*DN, bo + (size_t)l*DN,
                                Wl0 + (size_t)l*DN*DN, bl0 + (size_t)l*DN,
                                ln0_g + (size_t)l*DN, ln0_b + (size_t)l*DN,
                                Wm1 + (size_t)l*DN*DNH, Wm2 + (size_t)l*DNH*DN,
                                bm2 + (size_t)l*DN,
                                ln1_g + (size_t)l*DN, ln1_b + (size_t)l*DN);
        k_srctgt<<<BB*NN, 256>>>(Wsm + (size_t)l*DN*DEH, bsv + (size_t)l*DEH,
                                 Wtm + (size_t)l*DN*DEH, btv + (size_t)l*DEH);
        k_e1<<<BB*NN, 256, E1_SMEM_F*4>>>(e_in, e_out,
                                          We0 + (size_t)l*2*DE*DEH, be0 + (size_t)l*DEH,
                                          We1 + (size_t)l*DEH*DE, be1 + (size_t)l*DE,
                                          eln0_g + (size_t)l*DE, eln0_b + (size_t)l*DE);
        k_e2<<<BB*NN, 256, E2_SMEM_F*4>>>(e_out,
                                          Wem1 + (size_t)l*DE*DEH, Wem2 + (size_t)l*DEH*DE,
                                          bem2 + (size_t)l*DE,
                                          eln1_g + (size_t)l*DE, eln1_b + (size_t)l*DE);
        e_in = e_out;
        e_out = pe0;
    }

    int total = BB*NN*DN + BB*NN*NN*DE;
    k_final<<<(total + 255)/256, 256>>>(out);
}